// round 4
// baseline (speedup 1.0000x reference)
#include <cuda_runtime.h>

// YOLO v1 loss: S=7, NB=2, C=20. predictions [N, 7*7*30], targets [N,7,7,25].
// Output: scalar fp32 loss.
// Smem-staged streaming reduction: each 128-thread block stages 128 cells of
// pred (30 f32) + tgt (25 f32) via coalesced float4 loads, computes from smem.

#define S_ 7
#define C_ 20
#define CELL_PRED 30   // C + NB*5
#define CELL_TGT  25   // C + 5
#define LAMBDA_COORD 5.0f
#define LAMBDA_NOOBJ 0.5f
#define EPS_ 1e-6f
#define TPB 128

__global__ void yolo_zero_out(float* out) { out[0] = 0.0f; }

__device__ __forceinline__ float iou_mid(const float* a, const float* b) {
    float ax1 = a[0] - a[2] * 0.5f, ay1 = a[1] - a[3] * 0.5f;
    float ax2 = a[0] + a[2] * 0.5f, ay2 = a[1] + a[3] * 0.5f;
    float bx1 = b[0] - b[2] * 0.5f, by1 = b[1] - b[3] * 0.5f;
    float bx2 = b[0] + b[2] * 0.5f, by2 = b[1] + b[3] * 0.5f;
    float iw = fmaxf(fminf(ax2, bx2) - fmaxf(ax1, bx1), 0.0f);
    float ih = fmaxf(fminf(ay2, by2) - fmaxf(ay1, by1), 0.0f);
    float inter  = iw * ih;
    float area_a = fabsf((ax2 - ax1) * (ay2 - ay1));
    float area_b = fabsf((bx2 - bx1) * (by2 - by1));
    return inter / (area_a + area_b - inter + EPS_);
}

__global__ __launch_bounds__(TPB) void yolo_loss_kernel(
    const float* __restrict__ pred,
    const float* __restrict__ tgt,
    float* __restrict__ out,
    int total_cells,
    float invN)
{
    __shared__ float sp[TPB * CELL_PRED];   // 15360 B
    __shared__ float st[TPB * CELL_TGT];    // 12800 B

    const int cell0 = blockIdx.x * TPB;
    const int cells_here = min(TPB, total_cells - cell0);

    if (cells_here == TPB) {
        // Full block: perfectly coalesced float4 staging.
        // Base offsets: cell0*30*4 B and cell0*25*4 B — both multiples of 16
        // when cell0 is a multiple of TPB=128.
        const float4* gp = reinterpret_cast<const float4*>(pred + (size_t)cell0 * CELL_PRED);
        float4* sp4 = reinterpret_cast<float4*>(sp);
        #pragma unroll
        for (int i = threadIdx.x; i < TPB * CELL_PRED / 4; i += TPB)   // 960 float4
            sp4[i] = __ldg(gp + i);

        const float4* gt = reinterpret_cast<const float4*>(tgt + (size_t)cell0 * CELL_TGT);
        float4* st4 = reinterpret_cast<float4*>(st);
        #pragma unroll
        for (int i = threadIdx.x; i < TPB * CELL_TGT / 4; i += TPB)    // 800 float4
            st4[i] = __ldg(gt + i);
    } else {
        // Tail block: scalar staging with bounds.
        const float* gp = pred + (size_t)cell0 * CELL_PRED;
        for (int i = threadIdx.x; i < cells_here * CELL_PRED; i += TPB)
            sp[i] = __ldg(gp + i);
        const float* gt = tgt + (size_t)cell0 * CELL_TGT;
        for (int i = threadIdx.x; i < cells_here * CELL_TGT; i += TPB)
            st[i] = __ldg(gt + i);
    }
    __syncthreads();

    float v = 0.0f;
    if ((int)threadIdx.x < cells_here) {
        const float* p = sp + threadIdx.x * CELL_PRED;
        const float* t = st + threadIdx.x * CELL_TGT;

        // class loss
        float cls = 0.0f;
        #pragma unroll
        for (int c = 0; c < C_; c++) {
            float d = p[c] - t[c];
            cls = fmaf(d, d, cls);
        }

        bool obj = (t[C_] == 1.0f);

        float i1 = iou_mid(p + C_,     t + C_);
        float i2 = iou_mid(p + C_ + 5, t + C_);
        const float* r = (i1 > i2) ? (p + C_) : (p + C_ + 5);

        float dx = r[0] - t[C_ + 0];
        float dy = r[1] - t[C_ + 1];
        float xy = fmaf(dx, dx, dy * dy);
        float dw = sqrtf(r[2]) - sqrtf(t[C_ + 2]);
        float dh = sqrtf(r[3]) - sqrtf(t[C_ + 3]);
        float wh = fmaf(dw, dw, dh * dh);
        float coord = LAMBDA_COORD * (xy + wh);
        float dc = r[4] - t[C_ + 4];
        float conf = dc * dc;

        float c1 = p[C_ + 4];
        float c2 = p[C_ + 9];
        float noobj = LAMBDA_NOOBJ * fmaf(c1, c1, c2 * c2);

        v = obj ? (coord + conf + cls) : noobj;
        v *= invN;
    }

    // warp reduce
    #pragma unroll
    for (int off = 16; off > 0; off >>= 1)
        v += __shfl_down_sync(0xFFFFFFFFu, v, off);

    __shared__ float warp_sums[TPB / 32];
    int lane = threadIdx.x & 31;
    int wid  = threadIdx.x >> 5;
    if (lane == 0) warp_sums[wid] = v;
    __syncthreads();

    if (wid == 0) {
        float s = (lane < (TPB >> 5)) ? warp_sums[lane] : 0.0f;
        #pragma unroll
        for (int off = 2; off > 0; off >>= 1)
            s += __shfl_down_sync(0xFFFFFFFFu, s, off);
        if (lane == 0) atomicAdd(out, s);
    }
}

extern "C" void kernel_launch(void* const* d_in, const int* in_sizes, int n_in,
                              void* d_out, int out_size)
{
    const float* pred = (const float*)d_in[0];
    const float* tgt  = (const float*)d_in[1];
    float* out = (float*)d_out;

    int N = in_sizes[0] / (S_ * S_ * (C_ + 10));
    int total_cells = N * S_ * S_;
    float invN = 1.0f / (float)N;

    yolo_zero_out<<<1, 1>>>(out);

    int blocks = (total_cells + TPB - 1) / TPB;
    yolo_loss_kernel<<<blocks, TPB>>>(pred, tgt, out, total_cells, invN);
}

// round 7
// speedup vs baseline: 1.3255x; 1.3255x over previous
#include <cuda_runtime.h>
#include <cstdint>

// YOLO v1 loss: S=7, NB=2, C=20. predictions [N, 7*7*30], targets [N,7,7,25].
// Warp-private cp.async staging: each warp DMAs its 32 cells (coalesced 16B
// chunks, L1-bypass) into its own smem slice, __syncwarp, computes. No block
// barrier until the final reduce -> warps pipeline load vs compute naturally.

#define S_ 7
#define C_ 20
#define CELL_PRED 30   // C + NB*5
#define CELL_TGT  25   // C + 5
#define LAMBDA_COORD 5.0f
#define LAMBDA_NOOBJ 0.5f
#define EPS_ 1e-6f

#define TPB 256
#define WARPS (TPB / 32)
#define CELLS_PER_CTA 256            // 32 cells per warp
#define WARP_PRED_F4 240             // 32*30/4
#define WARP_TGT_F4  200             // 32*25/4
#define WARP_SLICE_F (32 * (CELL_PRED + CELL_TGT))   // 1760 floats = 7040 B

__global__ void yolo_zero_out(float* out) { out[0] = 0.0f; }

__device__ __forceinline__ void cp16(unsigned int smem_dst, const void* gmem_src) {
    asm volatile("cp.async.cg.shared.global [%0], [%1], 16;"
                 :: "r"(smem_dst), "l"(gmem_src));
}
__device__ __forceinline__ void cp_commit_wait() {
    asm volatile("cp.async.commit_group;");
    asm volatile("cp.async.wait_group 0;" ::: "memory");
}

__device__ __forceinline__ float iou_mid(const float* a, const float* b) {
    float ax1 = a[0] - a[2] * 0.5f, ay1 = a[1] - a[3] * 0.5f;
    float ax2 = a[0] + a[2] * 0.5f, ay2 = a[1] + a[3] * 0.5f;
    float bx1 = b[0] - b[2] * 0.5f, by1 = b[1] - b[3] * 0.5f;
    float bx2 = b[0] + b[2] * 0.5f, by2 = b[1] + b[3] * 0.5f;
    float iw = fmaxf(fminf(ax2, bx2) - fmaxf(ax1, bx1), 0.0f);
    float ih = fmaxf(fminf(ay2, by2) - fmaxf(ay1, by1), 0.0f);
    float inter  = iw * ih;
    float area_a = fabsf((ax2 - ax1) * (ay2 - ay1));
    float area_b = fabsf((bx2 - bx1) * (by2 - by1));
    return inter / (area_a + area_b - inter + EPS_);
}

__global__ __launch_bounds__(TPB) void yolo_loss_kernel(
    const float* __restrict__ pred,
    const float* __restrict__ tgt,
    float* __restrict__ out,
    int total_cells,
    float invN)
{
    __shared__ float smem[WARPS * WARP_SLICE_F];   // 56320 B
    __shared__ float warp_sums[WARPS];

    const int lane = threadIdx.x & 31;
    const int wid  = threadIdx.x >> 5;

    const int cell_base = blockIdx.x * CELLS_PER_CTA + wid * 32;

    float* wp = smem + wid * WARP_SLICE_F;           // [0:960) pred floats
    float* wt = wp + 32 * CELL_PRED;                 // [960:1760) tgt floats
    unsigned int wp_addr = (unsigned int)__cvta_generic_to_shared(wp);
    unsigned int wt_addr = (unsigned int)__cvta_generic_to_shared(wt);

    if (cell_base + 32 <= total_cells) {
        // Fast path: coalesced 16B cp.async, L1 bypass. Bases are 16B-aligned:
        // cell_base*120 and cell_base*100 are multiples of 16 (cell_base % 32 == 0).
        const float4* gp = reinterpret_cast<const float4*>(pred + (size_t)cell_base * CELL_PRED);
        #pragma unroll
        for (int i = 0; i < 8; i++) {
            int idx = lane + i * 32;
            if (idx < WARP_PRED_F4) cp16(wp_addr + idx * 16, gp + idx);
        }
        const float4* gt = reinterpret_cast<const float4*>(tgt + (size_t)cell_base * CELL_TGT);
        #pragma unroll
        for (int i = 0; i < 7; i++) {
            int idx = lane + i * 32;
            if (idx < WARP_TGT_F4) cp16(wt_addr + idx * 16, gt + idx);
        }
        cp_commit_wait();
    } else {
        // Tail path: guarded scalar staging.
        int cells_here = total_cells - cell_base;
        if (cells_here < 0) cells_here = 0;
        const float* gp = pred + (size_t)cell_base * CELL_PRED;
        for (int i = lane; i < cells_here * CELL_PRED; i += 32) wp[i] = __ldg(gp + i);
        const float* gt = tgt + (size_t)cell_base * CELL_TGT;
        for (int i = lane; i < cells_here * CELL_TGT; i += 32) wt[i] = __ldg(gt + i);
    }
    __syncwarp();

    float v = 0.0f;
    if (cell_base + lane < total_cells) {
        const float* p = wp + lane * CELL_PRED;
        const float* t = wt + lane * CELL_TGT;

        float cls = 0.0f;
        #pragma unroll
        for (int c = 0; c < C_; c++) {
            float d = p[c] - t[c];
            cls = fmaf(d, d, cls);
        }

        bool obj = (t[C_] == 1.0f);

        float i1 = iou_mid(p + C_,     t + C_);
        float i2 = iou_mid(p + C_ + 5, t + C_);
        const float* r = (i1 > i2) ? (p + C_) : (p + C_ + 5);

        float dx = r[0] - t[C_ + 0];
        float dy = r[1] - t[C_ + 1];
        float xy = fmaf(dx, dx, dy * dy);
        float dw = sqrtf(r[2]) - sqrtf(t[C_ + 2]);
        float dh = sqrtf(r[3]) - sqrtf(t[C_ + 3]);
        float wh = fmaf(dw, dw, dh * dh);
        float coord = LAMBDA_COORD * (xy + wh);
        float dc = r[4] - t[C_ + 4];
        float conf = dc * dc;

        float c1 = p[C_ + 4];
        float c2 = p[C_ + 9];
        float noobj = LAMBDA_NOOBJ * fmaf(c1, c1, c2 * c2);

        v = obj ? (coord + conf + cls) : noobj;
        v *= invN;
    }

    // warp reduce
    #pragma unroll
    for (int off = 16; off > 0; off >>= 1)
        v += __shfl_down_sync(0xFFFFFFFFu, v, off);
    if (lane == 0) warp_sums[wid] = v;
    __syncthreads();

    if (wid == 0) {
        float s = (lane < WARPS) ? warp_sums[lane] : 0.0f;
        #pragma unroll
        for (int off = 4; off > 0; off >>= 1)
            s += __shfl_down_sync(0xFFFFFFFFu, s, off);
        if (lane == 0) atomicAdd(out, s);
    }
}

extern "C" void kernel_launch(void* const* d_in, const int* in_sizes, int n_in,
                              void* d_out, int out_size)
{
    const float* pred = (const float*)d_in[0];
    const float* tgt  = (const float*)d_in[1];
    float* out = (float*)d_out;

    int N = in_sizes[0] / (S_ * S_ * (C_ + 10));
    int total_cells = N * S_ * S_;
    float invN = 1.0f / (float)N;

    yolo_zero_out<<<1, 1>>>(out);

    int blocks = (total_cells + CELLS_PER_CTA - 1) / CELLS_PER_CTA;
    yolo_loss_kernel<<<blocks, TPB>>>(pred, tgt, out, total_cells, invN);
}